// round 2
// baseline (speedup 1.0000x reference)
#include <cuda_runtime.h>
#include <cuda_bf16.h>

// Problem constants
#define Mm   1024
#define Nv   2048
#define DVd  3
#define DCd  6
#define Dd   8
#define Bb   128
#define Tt   5
#define CIN  48     // DC*D
#define VIN  25     // DV*D + 1
#define HC   192
#define HV   100

// Scratch activations (device globals; allocation in kernel_launch is forbidden).
// Layout is [group][feature][batch] for fully coalesced access.
__device__ float g_chk_in[Mm * CIN * Bb];   // [m][c][b], c = s*8+d
__device__ float g_var_x [Nv * VIN * Bb];   // [n][c][b], c = l*8+d, c=24 -> prior

__device__ __forceinline__ float gelu_exact(float v) {
    // jax.nn.gelu(approximate=False) == x * Phi(x)
    return v * normcdff(v);
}

// ---------------------------------------------------------------------------
// Init: chk_in = zeros with [...,s,0] = prior_llr[chk_nbrs[m,s]];
//       var_x[...,24] = prior_llr[n]
// ---------------------------------------------------------------------------
__global__ void init_chk(const float* __restrict__ prior,
                         const int*   __restrict__ chk_nbrs) {
    int i = blockIdx.x * 256 + threadIdx.x;
    if (i >= Mm * CIN * Bb) return;
    int c = (i >> 7) % CIN;           // i = m*CIN*128 + c*128 + b
    float v = 0.0f;
    if ((c & 7) == 0) {
        int m = i / (CIN * Bb);
        v = prior[chk_nbrs[m * DCd + (c >> 3)]];
    }
    g_chk_in[i] = v;
}

__global__ void init_var(const float* __restrict__ prior) {
    int i = blockIdx.x * 256 + threadIdx.x;     // n*128 + b
    if (i >= Nv * Bb) return;
    int n = i >> 7, b = i & 127;
    g_var_x[(size_t)n * (VIN * Bb) + 24 * Bb + b] = prior[n];
}

// ---------------------------------------------------------------------------
// Check kernel: one block per check m, one thread per batch row b.
// y = (gelu(x@W1+b1)@W2 + b2) * sgn ; scatter into g_var_x via v2c_gather.
// smem: W1[48][192] + W2[192][48] + b1[192] + b2[48] + idx[6]
// ---------------------------------------------------------------------------
#define CHK_SMEM_BYTES ((9216 + 9216 + 192 + 48) * 4 + 32)

__global__ __launch_bounds__(128, 3) void chk_kernel(
    const float* __restrict__ w1, const float* __restrict__ b1,
    const float* __restrict__ w2, const float* __restrict__ b2,
    const int*   __restrict__ synd, const int* __restrict__ v2c)
{
    const int m = blockIdx.x, b = threadIdx.x;
    extern __shared__ float sm[];
    float* sW1 = sm;                 // 9216
    float* sW2 = sm + 9216;          // 9216
    float* sb1 = sm + 18432;         // 192
    float* sb2 = sm + 18624;         // 48
    int*   sIdx = (int*)(sm + 18672);

    // Issue activation + syndrome loads early (overlap with smem fill)
    float x[CIN];
    const float* xin = g_chk_in + (size_t)m * (CIN * Bb) + b;
    #pragma unroll
    for (int i = 0; i < CIN; i++) x[i] = xin[i * Bb];
    const float sgn = 1.0f - 2.0f * (float)synd[b * Mm + m];

    {
        const float4* g1 = (const float4*)(w1 + (size_t)m * (CIN * HC));
        float4* s1 = (float4*)sW1;
        #pragma unroll 4
        for (int k = b; k < 2304; k += 128) s1[k] = g1[k];
        const float4* g2 = (const float4*)(w2 + (size_t)m * (HC * CIN));
        float4* s2 = (float4*)sW2;
        #pragma unroll 4
        for (int k = b; k < 2304; k += 128) s2[k] = g2[k];
        for (int k = b; k < HC; k += 128) sb1[k] = b1[m * HC + k];
        if (b < CIN) sb2[b] = b2[m * CIN + b];
        if (b < DCd) sIdx[b] = v2c[m * DCd + b];
    }
    __syncthreads();

    float y[CIN];
    #pragma unroll
    for (int c = 0; c < CIN; c++) y[c] = sb2[c];

    // Stream hidden layer through registers, 8 columns at a time.
    for (int jg = 0; jg < HC / 8; ++jg) {
        float h[8];
        #pragma unroll
        for (int u = 0; u < 8; u++) h[u] = sb1[jg * 8 + u];
        const float* base1 = sW1 + jg * 8;
        #pragma unroll
        for (int i = 0; i < CIN; i++) {
            float4 wa = *(const float4*)(base1 + i * HC);
            float4 wb = *(const float4*)(base1 + i * HC + 4);
            float xi = x[i];
            h[0] += xi * wa.x; h[1] += xi * wa.y; h[2] += xi * wa.z; h[3] += xi * wa.w;
            h[4] += xi * wb.x; h[5] += xi * wb.y; h[6] += xi * wb.z; h[7] += xi * wb.w;
        }
        #pragma unroll
        for (int u = 0; u < 8; u++) {
            float hu = gelu_exact(h[u]);
            const float4* wr = (const float4*)(sW2 + (jg * 8 + u) * CIN);
            #pragma unroll
            for (int q = 0; q < 12; q++) {
                float4 wv = wr[q];
                y[q * 4 + 0] += hu * wv.x; y[q * 4 + 1] += hu * wv.y;
                y[q * 4 + 2] += hu * wv.z; y[q * 4 + 3] += hu * wv.w;
            }
        }
    }

    // Scatter check-edge p = m*6+s to var-edge e = v2c[p]; conflict-free.
    #pragma unroll
    for (int s = 0; s < DCd; s++) {
        int e = sIdx[s];
        int n = e / 3, l = e - n * 3;
        float* dst = g_var_x + (size_t)n * (VIN * Bb) + (l * 8) * Bb + b;
        #pragma unroll
        for (int d = 0; d < 8; d++) dst[d * Bb] = y[s * 8 + d] * sgn;
    }
}

// ---------------------------------------------------------------------------
// Var kernel: one block per var n, one thread per batch row b.
// out = gelu(x@W1+b1)@W2 + b2 ; llr = out[24] -> d_out; msg -> g_chk_in.
// smem: W1[25][100] + W2 padded [100][28] + b1[100] + b2[25] + idx[3]
// ---------------------------------------------------------------------------
#define VAR_SMEM_BYTES (5432 * 4)

__global__ __launch_bounds__(128, 4) void var_kernel(
    const float* __restrict__ w1, const float* __restrict__ b1,
    const float* __restrict__ w2, const float* __restrict__ b2,
    const int*   __restrict__ c2v, float* __restrict__ out_llr)
{
    const int n = blockIdx.x, b = threadIdx.x;
    extern __shared__ float sm[];
    float* sW1 = sm;                 // 2500 = [25][100]
    float* sW2 = sm + 2500;          // 2800 = [100][28] (rows padded to 28)
    float* sb1 = sm + 5300;          // 100
    float* sb2 = sm + 5400;          // 25
    int*   sIdx = (int*)(sm + 5428); // 3

    float x[VIN];
    const float* xin = g_var_x + (size_t)n * (VIN * Bb) + b;
    #pragma unroll
    for (int i = 0; i < VIN; i++) x[i] = xin[i * Bb];

    {
        const float4* g1 = (const float4*)(w1 + (size_t)n * (VIN * HV));
        float4* s1 = (float4*)sW1;
        #pragma unroll 2
        for (int k = b; k < 625; k += 128) s1[k] = g1[k];
        const float* g2 = w2 + (size_t)n * (HV * VIN);
        for (int k = b; k < 2500; k += 128) {
            int r = k / 25, c = k - r * 25;
            sW2[r * 28 + c] = g2[k];
        }
        if (b < HV)  sb1[b] = b1[n * HV + b];
        if (b < VIN) sb2[b] = b2[n * VIN + b];
        if (b < DVd) sIdx[b] = c2v[n * DVd + b];
    }
    __syncthreads();

    float y[VIN];
    #pragma unroll
    for (int c = 0; c < VIN; c++) y[c] = sb2[c];

    // 12 hidden-column groups of 8
    for (int jg = 0; jg < 12; ++jg) {
        float h[8];
        #pragma unroll
        for (int u = 0; u < 8; u++) h[u] = sb1[jg * 8 + u];
        const float* base1 = sW1 + jg * 8;
        #pragma unroll
        for (int i = 0; i < VIN; i++) {
            float4 wa = *(const float4*)(base1 + i * HV);
            float4 wb = *(const float4*)(base1 + i * HV + 4);
            float xi = x[i];
            h[0] += xi * wa.x; h[1] += xi * wa.y; h[2] += xi * wa.z; h[3] += xi * wa.w;
            h[4] += xi * wb.x; h[5] += xi * wb.y; h[6] += xi * wb.z; h[7] += xi * wb.w;
        }
        #pragma unroll
        for (int u = 0; u < 8; u++) {
            float hu = gelu_exact(h[u]);
            const float* wr = sW2 + (jg * 8 + u) * 28;
            #pragma unroll
            for (int q = 0; q < 6; q++) {
                float4 wv = *(const float4*)(wr + q * 4);
                y[q * 4 + 0] += hu * wv.x; y[q * 4 + 1] += hu * wv.y;
                y[q * 4 + 2] += hu * wv.z; y[q * 4 + 3] += hu * wv.w;
            }
            y[24] += hu * wr[24];
        }
    }
    // tail: hidden columns 96..99
    {
        float h[4];
        #pragma unroll
        for (int u = 0; u < 4; u++) h[u] = sb1[96 + u];
        const float* base1 = sW1 + 96;
        #pragma unroll
        for (int i = 0; i < VIN; i++) {
            float4 wa = *(const float4*)(base1 + i * HV);
            float xi = x[i];
            h[0] += xi * wa.x; h[1] += xi * wa.y; h[2] += xi * wa.z; h[3] += xi * wa.w;
        }
        #pragma unroll
        for (int u = 0; u < 4; u++) {
            float hu = gelu_exact(h[u]);
            const float* wr = sW2 + (96 + u) * 28;
            #pragma unroll
            for (int q = 0; q < 6; q++) {
                float4 wv = *(const float4*)(wr + q * 4);
                y[q * 4 + 0] += hu * wv.x; y[q * 4 + 1] += hu * wv.y;
                y[q * 4 + 2] += hu * wv.z; y[q * 4 + 3] += hu * wv.w;
            }
            y[24] += hu * wr[24];
        }
    }

    // llr output: d_out layout [T,B,N], caller passes base + t*B*N
    out_llr[b * Nv + n] = y[24];

    // Scatter var-edge e = n*3+l to check-edge p = c2v[e]; conflict-free.
    #pragma unroll
    for (int l = 0; l < DVd; l++) {
        int p = sIdx[l];
        int mm = p / 6, s = p - mm * 6;
        float* dst = g_chk_in + (size_t)mm * (CIN * Bb) + (s * 8) * Bb + b;
        #pragma unroll
        for (int d = 0; d < 8; d++) dst[d * Bb] = y[l * 8 + d];
    }
}

// ---------------------------------------------------------------------------
extern "C" void kernel_launch(void* const* d_in, const int* in_sizes, int n_in,
                              void* d_out, int out_size)
{
    const int*   synd     = (const int*)  d_in[0];
    const float* prior    = (const float*)d_in[1];
    const float* cw1      = (const float*)d_in[2];
    const float* cb1      = (const float*)d_in[3];
    const float* cw2      = (const float*)d_in[4];
    const float* cb2      = (const float*)d_in[5];
    const float* vw1      = (const float*)d_in[6];
    const float* vb1      = (const float*)d_in[7];
    const float* vw2      = (const float*)d_in[8];
    const float* vb2      = (const float*)d_in[9];
    const int*   chk_nbrs = (const int*)  d_in[10];
    const int*   c2v      = (const int*)  d_in[11];
    const int*   v2c      = (const int*)  d_in[12];
    float* out = (float*)d_out;

    cudaFuncSetAttribute(chk_kernel, cudaFuncAttributeMaxDynamicSharedMemorySize,
                         CHK_SMEM_BYTES);
    cudaFuncSetAttribute(var_kernel, cudaFuncAttributeMaxDynamicSharedMemorySize,
                         VAR_SMEM_BYTES);

    init_chk<<<(Mm * CIN * Bb + 255) / 256, 256>>>(prior, chk_nbrs);
    init_var<<<(Nv * Bb + 255) / 256, 256>>>(prior);

    for (int t = 0; t < Tt; t++) {
        chk_kernel<<<Mm, 128, CHK_SMEM_BYTES>>>(cw1, cb1, cw2, cb2, synd, v2c);
        var_kernel<<<Nv, 128, VAR_SMEM_BYTES>>>(vw1, vb1, vw2, vb2, c2v,
                                                out + (size_t)t * Bb * Nv);
    }
}

// round 6
// speedup vs baseline: 1.1634x; 1.1634x over previous
#include <cuda_runtime.h>
#include <cuda_bf16.h>
#include <cstdint>

// Problem constants
#define Mm   1024
#define Nv   2048
#define DVd  3
#define DCd  6
#define Bb   128
#define Tt   5
#define CIN  48
#define VIN  25
#define HC   192
#define HV   100

// Scratch activations: layout [group][feature][batch] for coalesced access.
__device__ float g_chk_in[Mm * CIN * Bb];   // [m][c][b], c = s*8+d
__device__ float g_var_x [Nv * VIN * Bb];   // [n][c][b], c = l*8+d, c=24 -> prior

__device__ __forceinline__ float gelu_exact(float v) { return v * normcdff(v); }

// ---------------------------------------------------------------------------
// Packed f32x2 helpers (sm_100+ PTX; SASS FFMA2 — 2 fp32 FMAs per issue slot)
// ---------------------------------------------------------------------------
typedef unsigned long long u64t;

__device__ __forceinline__ u64t pk2(float a, float b) {
    u64t r; asm("mov.b64 %0, {%1, %2};" : "=l"(r) : "f"(a), "f"(b)); return r;
}
__device__ __forceinline__ u64t dup2(float a) {
    u64t r; asm("mov.b64 %0, {%1, %1};" : "=l"(r) : "f"(a)); return r;
}
__device__ __forceinline__ u64t f2fma(u64t a, u64t b, u64t c) {
    u64t d; asm("fma.rn.f32x2 %0, %1, %2, %3;" : "=l"(d) : "l"(a), "l"(b), "l"(c));
    return d;
}
__device__ __forceinline__ float2 upk(u64t v) {
    float2 r; asm("mov.b64 {%0, %1}, %2;" : "=f"(r.x), "=f"(r.y) : "l"(v)); return r;
}

// ---------------------------------------------------------------------------
// Init kernels
// ---------------------------------------------------------------------------
__global__ void init_chk(const float* __restrict__ prior,
                         const int*   __restrict__ chk_nbrs) {
    int i = blockIdx.x * 256 + threadIdx.x;
    if (i >= Mm * CIN * Bb) return;
    int c = (i >> 7) % CIN;
    float v = 0.0f;
    if ((c & 7) == 0) {
        int m = i / (CIN * Bb);
        v = prior[chk_nbrs[m * DCd + (c >> 3)]];
    }
    g_chk_in[i] = v;
}
__global__ void init_var(const float* __restrict__ prior) {
    int i = blockIdx.x * 256 + threadIdx.x;
    if (i >= Nv * Bb) return;
    int n = i >> 7, b = i & 127;
    g_var_x[(size_t)n * (VIN * Bb) + 24 * Bb + b] = prior[n];
}

// ---------------------------------------------------------------------------
// Check kernel: one block per check m, one thread per batch row b.
// f32x2-packed along the output-column dimension.
// ---------------------------------------------------------------------------
#define CHK_SMEM_BYTES ((9216 + 9216 + 192 + 48) * 4 + 32)

__global__ __launch_bounds__(128, 3) void chk_kernel(
    const float* __restrict__ w1, const float* __restrict__ b1,
    const float* __restrict__ w2, const float* __restrict__ b2,
    const int*   __restrict__ synd, const int* __restrict__ v2c)
{
    const int m = blockIdx.x, b = threadIdx.x;
    extern __shared__ float sm[];
    float* sW1 = sm;                 // [48][192]
    float* sW2 = sm + 9216;          // [192][48]
    float* sb1 = sm + 18432;
    float* sb2 = sm + 18624;
    int*   sIdx = (int*)(sm + 18672);

    float x[CIN];
    const float* xin = g_chk_in + (size_t)m * (CIN * Bb) + b;
    #pragma unroll
    for (int i = 0; i < CIN; i++) x[i] = xin[i * Bb];
    const float sgn = 1.0f - 2.0f * (float)synd[b * Mm + m];

    {
        const float4* g1 = (const float4*)(w1 + (size_t)m * (CIN * HC));
        float4* s1 = (float4*)sW1;
        #pragma unroll 4
        for (int k = b; k < 2304; k += 128) s1[k] = g1[k];
        const float4* g2 = (const float4*)(w2 + (size_t)m * (HC * CIN));
        float4* s2 = (float4*)sW2;
        #pragma unroll 4
        for (int k = b; k < 2304; k += 128) s2[k] = g2[k];
        for (int k = b; k < HC; k += 128) sb1[k] = b1[m * HC + k];
        if (b < CIN) sb2[b] = b2[m * CIN + b];
        if (b < DCd) sIdx[b] = v2c[m * DCd + b];
    }
    __syncthreads();

    // y: 48 outputs as 24 packed pairs
    u64t y2[24];
    #pragma unroll
    for (int q = 0; q < 24; q++) y2[q] = *(const u64t*)(sb2 + 2 * q);

    // 12 groups of 16 hidden columns
    for (int jg = 0; jg < 12; ++jg) {
        u64t h2[8];
        #pragma unroll
        for (int u = 0; u < 8; u++) h2[u] = *(const u64t*)(sb1 + jg * 16 + 2 * u);

        const float* base1 = sW1 + jg * 16;
        #pragma unroll
        for (int i = 0; i < CIN; i++) {
            u64t xx = dup2(x[i]);
            const ulonglong2* wr = (const ulonglong2*)(base1 + i * HC);
            ulonglong2 p0 = wr[0], p1 = wr[1], p2 = wr[2], p3 = wr[3];
            h2[0] = f2fma(xx, p0.x, h2[0]); h2[1] = f2fma(xx, p0.y, h2[1]);
            h2[2] = f2fma(xx, p1.x, h2[2]); h2[3] = f2fma(xx, p1.y, h2[3]);
            h2[4] = f2fma(xx, p2.x, h2[4]); h2[5] = f2fma(xx, p2.y, h2[5]);
            h2[6] = f2fma(xx, p3.x, h2[6]); h2[7] = f2fma(xx, p3.y, h2[7]);
        }
        #pragma unroll
        for (int u = 0; u < 8; u++) {
            float2 hv = upk(h2[u]);
            u64t g0 = dup2(gelu_exact(hv.x));
            u64t g1 = dup2(gelu_exact(hv.y));
            const ulonglong2* r0 = (const ulonglong2*)(sW2 + (jg * 16 + 2 * u)     * CIN);
            const ulonglong2* r1 = (const ulonglong2*)(sW2 + (jg * 16 + 2 * u + 1) * CIN);
            #pragma unroll
            for (int q = 0; q < 12; q++) {
                ulonglong2 a = r0[q];
                y2[2 * q]     = f2fma(g0, a.x, y2[2 * q]);
                y2[2 * q + 1] = f2fma(g0, a.y, y2[2 * q + 1]);
                ulonglong2 c = r1[q];
                y2[2 * q]     = f2fma(g1, c.x, y2[2 * q]);
                y2[2 * q + 1] = f2fma(g1, c.y, y2[2 * q + 1]);
            }
        }
    }

    float y[CIN];
    #pragma unroll
    for (int q = 0; q < 24; q++) {
        float2 v = upk(y2[q]);
        y[2 * q] = v.x * sgn; y[2 * q + 1] = v.y * sgn;
    }

    // Scatter check-edge p = m*6+s to var-edge e = v2c[p]; conflict-free.
    #pragma unroll
    for (int s = 0; s < DCd; s++) {
        int e = sIdx[s];
        int n = e / 3, l = e - n * 3;
        float* dst = g_var_x + (size_t)n * (VIN * Bb) + (l * 8) * Bb + b;
        #pragma unroll
        for (int d = 0; d < 8; d++) dst[d * Bb] = y[s * 8 + d];
    }
}

// ---------------------------------------------------------------------------
// Var kernel: one block per var n, one thread per batch row b. f32x2-packed.
// ---------------------------------------------------------------------------
#define VAR_SMEM_BYTES (5432 * 4)

__global__ __launch_bounds__(128, 5) void var_kernel(
    const float* __restrict__ w1, const float* __restrict__ b1,
    const float* __restrict__ w2, const float* __restrict__ b2,
    const int*   __restrict__ c2v, float* __restrict__ out_llr)
{
    const int n = blockIdx.x, b = threadIdx.x;
    extern __shared__ float sm[];
    float* sW1 = sm;                 // [25][100]
    float* sW2 = sm + 2500;          // [100][28] rows padded to 28
    float* sb1 = sm + 5300;
    float* sb2 = sm + 5400;
    int*   sIdx = (int*)(sm + 5428);

    float x[VIN];
    const float* xin = g_var_x + (size_t)n * (VIN * Bb) + b;
    #pragma unroll
    for (int i = 0; i < VIN; i++) x[i] = xin[i * Bb];

    {
        const float4* g1 = (const float4*)(w1 + (size_t)n * (VIN * HV));
        float4* s1 = (float4*)sW1;
        #pragma unroll 2
        for (int k = b; k < 625; k += 128) s1[k] = g1[k];
        const float* g2 = w2 + (size_t)n * (HV * VIN);
        for (int k = b; k < 2500; k += 128) {
            int r = k / 25, c = k - r * 25;
            sW2[r * 28 + c] = g2[k];
        }
        if (b < HV)  sb1[b] = b1[n * HV + b];
        if (b < VIN) sb2[b] = b2[n * VIN + b];
        if (b < DVd) sIdx[b] = c2v[n * DVd + b];
    }
    __syncthreads();

    u64t y2[12];
    #pragma unroll
    for (int q = 0; q < 12; q++) y2[q] = *(const u64t*)(sb2 + 2 * q);
    float y24 = sb2[24];

    // 6 groups of 16 hidden columns
    for (int jg = 0; jg < 6; ++jg) {
        u64t h2[8];
        #pragma unroll
        for (int u = 0; u < 8; u++) h2[u] = *(const u64t*)(sb1 + jg * 16 + 2 * u);

        const float* base1 = sW1 + jg * 16;
        #pragma unroll
        for (int i = 0; i < VIN; i++) {
            u64t xx = dup2(x[i]);
            const ulonglong2* wr = (const ulonglong2*)(base1 + i * HV);
            ulonglong2 p0 = wr[0], p1 = wr[1], p2 = wr[2], p3 = wr[3];
            h2[0] = f2fma(xx, p0.x, h2[0]); h2[1] = f2fma(xx, p0.y, h2[1]);
            h2[2] = f2fma(xx, p1.x, h2[2]); h2[3] = f2fma(xx, p1.y, h2[3]);
            h2[4] = f2fma(xx, p2.x, h2[4]); h2[5] = f2fma(xx, p2.y, h2[5]);
            h2[6] = f2fma(xx, p3.x, h2[6]); h2[7] = f2fma(xx, p3.y, h2[7]);
        }
        #pragma unroll
        for (int u = 0; u < 8; u++) {
            float2 hv = upk(h2[u]);
            float ga = gelu_exact(hv.x), gb = gelu_exact(hv.y);
            u64t g0 = dup2(ga), g1 = dup2(gb);
            const float* r0f = sW2 + (jg * 16 + 2 * u) * 28;
            const float* r1f = sW2 + (jg * 16 + 2 * u + 1) * 28;
            const ulonglong2* r0 = (const ulonglong2*)r0f;
            const ulonglong2* r1 = (const ulonglong2*)r1f;
            #pragma unroll
            for (int q = 0; q < 6; q++) {
                ulonglong2 a = r0[q];
                y2[2 * q]     = f2fma(g0, a.x, y2[2 * q]);
                y2[2 * q + 1] = f2fma(g0, a.y, y2[2 * q + 1]);
                ulonglong2 c = r1[q];
                y2[2 * q]     = f2fma(g1, c.x, y2[2 * q]);
                y2[2 * q + 1] = f2fma(g1, c.y, y2[2 * q + 1]);
            }
            y24 += ga * r0f[24];
            y24 += gb * r1f[24];
        }
    }
    // tail: hidden columns 96..99
    {
        u64t h2[2];
        #pragma unroll
        for (int u = 0; u < 2; u++) h2[u] = *(const u64t*)(sb1 + 96 + 2 * u);
        const float* base1 = sW1 + 96;
        #pragma unroll
        for (int i = 0; i < VIN; i++) {
            u64t xx = dup2(x[i]);
            const ulonglong2* wr = (const ulonglong2*)(base1 + i * HV);
            ulonglong2 p0 = wr[0];
            h2[0] = f2fma(xx, p0.x, h2[0]); h2[1] = f2fma(xx, p0.y, h2[1]);
        }
        #pragma unroll
        for (int u = 0; u < 2; u++) {
            float2 hv = upk(h2[u]);
            float ga = gelu_exact(hv.x), gb = gelu_exact(hv.y);
            u64t g0 = dup2(ga), g1 = dup2(gb);
            const float* r0f = sW2 + (96 + 2 * u) * 28;
            const float* r1f = sW2 + (96 + 2 * u + 1) * 28;
            const ulonglong2* r0 = (const ulonglong2*)r0f;
            const ulonglong2* r1 = (const ulonglong2*)r1f;
            #pragma unroll
            for (int q = 0; q < 6; q++) {
                ulonglong2 a = r0[q];
                y2[2 * q]     = f2fma(g0, a.x, y2[2 * q]);
                y2[2 * q + 1] = f2fma(g0, a.y, y2[2 * q + 1]);
                ulonglong2 c = r1[q];
                y2[2 * q]     = f2fma(g1, c.x, y2[2 * q]);
                y2[2 * q + 1] = f2fma(g1, c.y, y2[2 * q + 1]);
            }
            y24 += ga * r0f[24];
            y24 += gb * r1f[24];
        }
    }

    float y[24];
    #pragma unroll
    for (int q = 0; q < 12; q++) {
        float2 v = upk(y2[q]);
        y[2 * q] = v.x; y[2 * q + 1] = v.y;
    }

    out_llr[b * Nv + n] = y24;

    // Scatter var-edge e = n*3+l to check-edge p = c2v[e]; conflict-free.
    #pragma unroll
    for (int l = 0; l < DVd; l++) {
        int p = sIdx[l];
        int mm = p / 6, s = p - mm * 6;
        float* dst = g_chk_in + (size_t)mm * (CIN * Bb) + (s * 8) * Bb + b;
        #pragma unroll
        for (int d = 0; d < 8; d++) dst[d * Bb] = y[l * 8 + d];
    }
}

// ---------------------------------------------------------------------------
extern "C" void kernel_launch(void* const* d_in, const int* in_sizes, int n_in,
                              void* d_out, int out_size)
{
    const int*   synd     = (const int*)  d_in[0];
    const float* prior    = (const float*)d_in[1];
    const float* cw1      = (const float*)d_in[2];
    const float* cb1      = (const float*)d_in[3];
    const float* cw2      = (const float*)d_in[4];
    const float* cb2      = (const float*)d_in[5];
    const float* vw1      = (const float*)d_in[6];
    const float* vb1      = (const float*)d_in[7];
    const float* vw2      = (const float*)d_in[8];
    const float* vb2      = (const float*)d_in[9];
    const int*   chk_nbrs = (const int*)  d_in[10];
    const int*   c2v      = (const int*)  d_in[11];
    const int*   v2c      = (const int*)  d_in[12];
    float* out = (float*)d_out;

    cudaFuncSetAttribute(chk_kernel, cudaFuncAttributeMaxDynamicSharedMemorySize,
                         CHK_SMEM_BYTES);
    cudaFuncSetAttribute(var_kernel, cudaFuncAttributeMaxDynamicSharedMemorySize,
                         VAR_SMEM_BYTES);

    init_chk<<<(Mm * CIN * Bb + 255) / 256, 256>>>(prior, chk_nbrs);
    init_var<<<(Nv * Bb + 255) / 256, 256>>>(prior);

    for (int t = 0; t < Tt; t++) {
        chk_kernel<<<Mm, 128, CHK_SMEM_BYTES>>>(cw1, cb1, cw2, cb2, synd, v2c);
        var_kernel<<<Nv, 128, VAR_SMEM_BYTES>>>(vw1, vb1, vw2, vb2, c2v,
                                                out + (size_t)t * Bb * Nv);
    }
}